// round 3
// baseline (speedup 1.0000x reference)
#include <cuda_runtime.h>
#include <cuda_bf16.h>
#include <math.h>

// ---------------- problem constants ----------------
constexpr int BS  = 8;            // batch
constexpr int C   = 128;          // channels
constexpr int HH  = 128;
constexpr int WW  = 128;
constexpr int P   = HH * WW;      // 16384 tokens per image
constexpr long long M = (long long)BS * P;  // 131072 rows
constexpr int HID = 512;          // 4*C

// ---------------- device scratch (static: no runtime allocation) ----------------
__device__ float g_xt  [(size_t)M * C];     // residual stream after conv     (B,P,C)
__device__ float g_xn  [(size_t)M * C];     // LN output (reused ln1/ln2)
__device__ float g_qkv [(size_t)M * 3 * C]; // qkv projection                 (B,P,384)
__device__ float g_abuf[(size_t)M * C];     // attention output               (B,P,C)
__device__ float g_xt2 [(size_t)M * C];     // residual after attn branch
__device__ float g_h   [(size_t)M * HID];   // gelu(fc1)
__device__ float g_y   [(size_t)M * C];     // final pre-transpose

// =================================================================
// Kernel 1: depthwise 3x3 conv (cross-correlation, SAME zero pad) +
//           bias + residual, write transposed to (B, P, C)
// block: (b, h, cblock(32), wblock(32)); 256 threads
// =================================================================
__global__ __launch_bounds__(256) void conv_kernel(
    const float* __restrict__ x, const float* __restrict__ cw,
    const float* __restrict__ cb, float* __restrict__ xt)
{
    int b  = blockIdx.z;
    int h  = blockIdx.y;
    int c0 = (blockIdx.x >> 2) * 32;
    int w0 = (blockIdx.x & 3) * 32;
    __shared__ float sx[32][3][36];   // [c][dy][w-1..w+32]
    __shared__ float so[32][33];      // [c][w] output tile (padded)
    int tid = threadIdx.x;

    // load halo patch (32 ch x 3 rows x 34 w)
    for (int i = tid; i < 32 * 3 * 34; i += 256) {
        int c  = i / (3 * 34);
        int r  = (i / 34) % 3;
        int wi = i % 34;
        int hh = h + r - 1;
        int wg = w0 + wi - 1;
        float v = 0.f;
        if (hh >= 0 && hh < HH && wg >= 0 && wg < WW)
            v = x[(((size_t)b * C + c0 + c) * HH + hh) * WW + wg];
        sx[c][r][wi] = v;
    }
    __syncthreads();

    // compute: thread -> channel c (32), 4 w positions
    int c     = tid >> 3;
    int wbase = (tid & 7) * 4;
    const float* wg9 = cw + (size_t)(c0 + c) * 9;
    float w00 = wg9[0], w01 = wg9[1], w02 = wg9[2];
    float w10 = wg9[3], w11 = wg9[4], w12 = wg9[5];
    float w20 = wg9[6], w21 = wg9[7], w22 = wg9[8];
    float bias = cb[c0 + c];
#pragma unroll
    for (int j = 0; j < 4; j++) {
        int wi = wbase + j;
        float acc = sx[c][0][wi] * w00 + sx[c][0][wi+1] * w01 + sx[c][0][wi+2] * w02
                  + sx[c][1][wi] * w10 + sx[c][1][wi+1] * w11 + sx[c][1][wi+2] * w12
                  + sx[c][2][wi] * w20 + sx[c][2][wi+1] * w21 + sx[c][2][wi+2] * w22;
        so[c][wi] = acc + bias + sx[c][1][wi+1];   // + x (residual)
    }
    __syncthreads();

    // write transposed: consecutive lanes -> consecutive channels (coalesced)
    int cc = tid & 31;
    for (int wr = tid >> 5; wr < 32; wr += 8) {
        xt[((size_t)b * P + (size_t)h * WW + w0 + wr) * C + c0 + cc] = so[cc][wr];
    }
}

// =================================================================
// Kernel 2: LayerNorm over C=128, one warp per token
// =================================================================
__global__ __launch_bounds__(256) void ln_kernel(
    const float* __restrict__ in, const float* __restrict__ w,
    const float* __restrict__ b, float* __restrict__ out)
{
    size_t t  = (size_t)blockIdx.x * 8 + (threadIdx.x >> 5);
    int lane  = threadIdx.x & 31;
    const float4* row = (const float4*)(in + t * C);
    float4 v = row[lane];
    float s = v.x + v.y + v.z + v.w;
#pragma unroll
    for (int o = 16; o; o >>= 1) s += __shfl_xor_sync(0xffffffffu, s, o);
    float mean = s * (1.f / 128.f);
    float dx = v.x - mean, dy = v.y - mean, dz = v.z - mean, dw = v.w - mean;
    float vs = dx*dx + dy*dy + dz*dz + dw*dw;
#pragma unroll
    for (int o = 16; o; o >>= 1) vs += __shfl_xor_sync(0xffffffffu, vs, o);
    float rstd = rsqrtf(vs * (1.f / 128.f) + 1e-5f);
    float4 wv = ((const float4*)w)[lane];
    float4 bv = ((const float4*)b)[lane];
    float4 o4;
    o4.x = dx * rstd * wv.x + bv.x;
    o4.y = dy * rstd * wv.y + bv.y;
    o4.z = dz * rstd * wv.z + bv.z;
    o4.w = dw * rstd * wv.w + bv.w;
    ((float4*)(out + t * C))[lane] = o4;
}

// =================================================================
// Templated fp32 SGEMM: 128x128 block tile, BK=8, 256 threads,
// 8x8 micro-tile split 4+4 (conflict-free LDS.128 frags),
// global prefetch across k-tiles. Epilogue fused via functor.
// =================================================================
constexpr int BM = 128, BN = 128, BK = 8;

struct EpiQKV {
    float* out;
    __device__ __forceinline__ void store(size_t row, int col, float4 v) const {
        *(float4*)(out + row * 384 + col) = v;
    }
};
struct EpiProj {   // out = resid + ls * (v + bias)
    const float* bias; const float* ls; const float* resid; float* out;
    __device__ __forceinline__ void store(size_t row, int col, float4 v) const {
        float4 bb = *(const float4*)(bias + col);
        float4 ss = *(const float4*)(ls + col);
        float4 rr = *(const float4*)(resid + row * 128 + col);
        float4 o;
        o.x = rr.x + ss.x * (v.x + bb.x);
        o.y = rr.y + ss.y * (v.y + bb.y);
        o.z = rr.z + ss.z * (v.z + bb.z);
        o.w = rr.w + ss.w * (v.w + bb.w);
        *(float4*)(out + row * 128 + col) = o;
    }
};
struct EpiGelu {   // out = gelu_exact(v + bias), N = 512
    const float* bias; float* out;
    __device__ __forceinline__ float gelu(float g) const {
        return 0.5f * g * (1.f + erff(g * 0.70710678118654752f));
    }
    __device__ __forceinline__ void store(size_t row, int col, float4 v) const {
        float4 bb = *(const float4*)(bias + col);
        float4 o;
        o.x = gelu(v.x + bb.x);
        o.y = gelu(v.y + bb.y);
        o.z = gelu(v.z + bb.z);
        o.w = gelu(v.w + bb.w);
        *(float4*)(out + row * 512 + col) = o;
    }
};
struct EpiFc2 {    // out = resid + ls * (v + bias), N = 128
    const float* bias; const float* ls; const float* resid; float* out;
    __device__ __forceinline__ void store(size_t row, int col, float4 v) const {
        float4 bb = *(const float4*)(bias + col);
        float4 ss = *(const float4*)(ls + col);
        float4 rr = *(const float4*)(resid + row * 128 + col);
        float4 o;
        o.x = rr.x + ss.x * (v.x + bb.x);
        o.y = rr.y + ss.y * (v.y + bb.y);
        o.z = rr.z + ss.z * (v.z + bb.z);
        o.w = rr.w + ss.w * (v.w + bb.w);
        *(float4*)(out + row * 128 + col) = o;
    }
};

template <class Epi>
__global__ __launch_bounds__(256, 2) void sgemm_kernel(
    const float* __restrict__ A, const float* __restrict__ Bg,
    int K, int N, Epi epi)
{
    __shared__ float As[BK][BM + 4];
    __shared__ float Bs[BK][BN];
    int tid = threadIdx.x;
    size_t rowBase = (size_t)blockIdx.y * BM;
    int    colBase = blockIdx.x * BN;

    int aRow = tid >> 1;          // 0..127
    int aCol = (tid & 1) * 4;     // 0 / 4
    int bRow = tid >> 5;          // 0..7
    int bCol = (tid & 31) * 4;    // 0..124

    const float* Aptr = A + (rowBase + aRow) * K + aCol;
    const float* Bptr = Bg + (size_t)bRow * N + colBase + bCol;

    int ty = tid >> 4;            // 0..15 -> rows
    int tx = tid & 15;            // 0..15 -> cols

    float acc[8][8];
#pragma unroll
    for (int i = 0; i < 8; i++)
#pragma unroll
        for (int j = 0; j < 8; j++) acc[i][j] = 0.f;

    float4 av = *(const float4*)Aptr;
    float4 bv = *(const float4*)Bptr;

    for (int k0 = 0; k0 < K; k0 += BK) {
        __syncthreads();
        As[aCol + 0][aRow] = av.x;
        As[aCol + 1][aRow] = av.y;
        As[aCol + 2][aRow] = av.z;
        As[aCol + 3][aRow] = av.w;
        *(float4*)&Bs[bRow][bCol] = bv;
        if (k0 + BK < K) {
            Aptr += BK;
            Bptr += (size_t)BK * N;
            av = *(const float4*)Aptr;
            bv = *(const float4*)Bptr;
        }
        __syncthreads();
#pragma unroll
        for (int k = 0; k < BK; k++) {
            float ar[8], br[8];
            *(float4*)&ar[0] = *(const float4*)&As[k][ty * 4];
            *(float4*)&ar[4] = *(const float4*)&As[k][64 + ty * 4];
            *(float4*)&br[0] = *(const float4*)&Bs[k][tx * 4];
            *(float4*)&br[4] = *(const float4*)&Bs[k][64 + tx * 4];
#pragma unroll
            for (int i = 0; i < 8; i++)
#pragma unroll
                for (int j = 0; j < 8; j++)
                    acc[i][j] = fmaf(ar[i], br[j], acc[i][j]);
        }
    }

#pragma unroll
    for (int ih = 0; ih < 2; ih++)
#pragma unroll
        for (int ii = 0; ii < 4; ii++) {
            size_t row = rowBase + ih * 64 + ty * 4 + ii;
#pragma unroll
            for (int jh = 0; jh < 2; jh++) {
                int i = ih * 4 + ii;
                float4 v = make_float4(acc[i][jh*4+0], acc[i][jh*4+1],
                                       acc[i][jh*4+2], acc[i][jh*4+3]);
                epi.store(row, colBase + jh * 64 + tx * 4, v);
            }
        }
}

// =================================================================
// Window attention: 8x8 windows (64 tokens), heads 0..3, hd=16.
// One CTA per (b, wy, wx); 256 thr = 4 heads x 64 queries.
// Single-pass softmax (scores are O(1): no overflow risk).
// =================================================================
__global__ __launch_bounds__(256) void win_attn_kernel(
    const float* __restrict__ qkv, float* __restrict__ abuf)
{
    int blk = blockIdx.x;
    int b  = blk >> 8;
    int wy = (blk >> 4) & 15;
    int wx = blk & 15;
    int tid = threadIdx.x;
    int l = tid >> 6;       // head 0..3
    int i = tid & 63;       // query index in window
    int y = i >> 3, x = i & 7;
    size_t p = (size_t)(wy * 8 + y) * WW + wx * 8 + x;
    const float* base = qkv + ((size_t)b * P + p) * 384;

    __shared__ float sk[4][64][16];
    __shared__ float sv[4][64][16];

    {   // each thread stages its own K,V row
        const float4* kg = (const float4*)(base + 128 + l * 16);
        const float4* vg = (const float4*)(base + 256 + l * 16);
        float4* kd = (float4*)sk[l][i];
        float4* vd = (float4*)sv[l][i];
        kd[0] = kg[0]; kd[1] = kg[1]; kd[2] = kg[2]; kd[3] = kg[3];
        vd[0] = vg[0]; vd[1] = vg[1]; vd[2] = vg[2]; vd[3] = vg[3];
    }
    const float4* qg = (const float4*)(base + l * 16);
    float4 q0 = qg[0], q1 = qg[1], q2 = qg[2], q3 = qg[3];
    __syncthreads();

    float4 o0 = {0,0,0,0}, o1 = {0,0,0,0}, o2 = {0,0,0,0}, o3 = {0,0,0,0};
    float lsum = 0.f;
    const float scale = 0.25f;   // hd^-0.5

    for (int j = 0; j < 64; j++) {
        const float4* kr = (const float4*)sk[l][j];
        float4 ka = kr[0], kb = kr[1], kc = kr[2], kd = kr[3];
        float s = q0.x*ka.x + q0.y*ka.y + q0.z*ka.z + q0.w*ka.w
                + q1.x*kb.x + q1.y*kb.y + q1.z*kb.z + q1.w*kb.w
                + q2.x*kc.x + q2.y*kc.y + q2.z*kc.z + q2.w*kc.w
                + q3.x*kd.x + q3.y*kd.y + q3.z*kd.z + q3.w*kd.w;
        float e = __expf(s * scale);
        lsum += e;
        const float4* vr = (const float4*)sv[l][j];
        float4 va = vr[0], vb = vr[1], vc = vr[2], vd = vr[3];
        o0.x += e*va.x; o0.y += e*va.y; o0.z += e*va.z; o0.w += e*va.w;
        o1.x += e*vb.x; o1.y += e*vb.y; o1.z += e*vb.z; o1.w += e*vb.w;
        o2.x += e*vc.x; o2.y += e*vc.y; o2.z += e*vc.z; o2.w += e*vc.w;
        o3.x += e*vd.x; o3.y += e*vd.y; o3.z += e*vd.z; o3.w += e*vd.w;
    }
    float inv = 1.f / lsum;
    float4* ob = (float4*)(abuf + ((size_t)b * P + p) * C + l * 16);
    ob[0] = make_float4(o0.x*inv, o0.y*inv, o0.z*inv, o0.w*inv);
    ob[1] = make_float4(o1.x*inv, o1.y*inv, o1.z*inv, o1.w*inv);
    ob[2] = make_float4(o2.x*inv, o2.y*inv, o2.z*inv, o2.w*inv);
    ob[3] = make_float4(o3.x*inv, o3.y*inv, o3.z*inv, o3.w*inv);
}

// =================================================================
// Grid attention: seq = 256 window positions, heads 4..7.
// One CTA per (b, in-window pos, head); 256 thr = 256 queries.
// =================================================================
__global__ __launch_bounds__(256) void grid_attn_kernel(
    const float* __restrict__ qkv, float* __restrict__ abuf)
{
    int blk = blockIdx.x;
    int b   = blk >> 8;
    int pos = (blk >> 2) & 63;  // y*8+x within window
    int g   = blk & 3;          // local head index of global group
    int y = pos >> 3, x = pos & 7;
    int tid = threadIdx.x;      // sequence index j = wy*16+wx
    int wy = tid >> 4, wx = tid & 15;
    size_t p = (size_t)(wy * 8 + y) * WW + wx * 8 + x;
    const float* base = qkv + ((size_t)b * P + p) * 384;
    int hc = (4 + g) * 16;

    __shared__ float sk[256][16];
    __shared__ float sv[256][16];

    {
        const float4* kg = (const float4*)(base + 128 + hc);
        const float4* vg = (const float4*)(base + 256 + hc);
        float4* kd = (float4*)sk[tid];
        float4* vd = (float4*)sv[tid];
        kd[0] = kg[0]; kd[1] = kg[1]; kd[2] = kg[2]; kd[3] = kg[3];
        vd[0] = vg[0]; vd[1] = vg[1]; vd[2] = vg[2]; vd[3] = vg[3];
    }
    const float4* qg = (const float4*)(base + hc);
    float4 q0 = qg[0], q1 = qg[1], q2 = qg[2], q3 = qg[3];
    __syncthreads();

    float4 o0 = {0,0,0,0}, o1 = {0,0,0,0}, o2 = {0,0,0,0}, o3 = {0,0,0,0};
    float lsum = 0.f;
    const float scale = 0.25f;

    for (int j = 0; j < 256; j++) {
        const float4* kr = (const float4*)sk[j];
        float4 ka = kr[0], kb = kr[1], kc = kr[2], kd = kr[3];
        float s = q0.x*ka.x + q0.y*ka.y + q0.z*ka.z + q0.w*ka.w
                + q1.x*kb.x + q1.y*kb.y + q1.z*kb.z + q1.w*kb.w
                + q2.x*kc.x + q2.y*kc.y + q2.z*kc.z + q2.w*kc.w
                + q3.x*kd.x + q3.y*kd.y + q3.z*kd.z + q3.w*kd.w;
        float e = __expf(s * scale);
        lsum += e;
        const float4* vr = (const float4*)sv[j];
        float4 va = vr[0], vb = vr[1], vc = vr[2], vd = vr[3];
        o0.x += e*va.x; o0.y += e*va.y; o0.z += e*va.z; o0.w += e*va.w;
        o1.x += e*vb.x; o1.y += e*vb.y; o1.z += e*vb.z; o1.w += e*vb.w;
        o2.x += e*vc.x; o2.y += e*vc.y; o2.z += e*vc.z; o2.w += e*vc.w;
        o3.x += e*vd.x; o3.y += e*vd.y; o3.z += e*vd.z; o3.w += e*vd.w;
    }
    float inv = 1.f / lsum;
    float4* ob = (float4*)(abuf + ((size_t)b * P + p) * C + 64 + g * 16);
    ob[0] = make_float4(o0.x*inv, o0.y*inv, o0.z*inv, o0.w*inv);
    ob[1] = make_float4(o1.x*inv, o1.y*inv, o1.z*inv, o1.w*inv);
    ob[2] = make_float4(o2.x*inv, o2.y*inv, o2.z*inv, o2.w*inv);
    ob[3] = make_float4(o3.x*inv, o3.y*inv, o3.z*inv, o3.w*inv);
}

// =================================================================
// Final transpose: (B, P, C) -> (B, C, P) into d_out
// =================================================================
__global__ void transpose_out_kernel(const float* __restrict__ y,
                                     float* __restrict__ out)
{
    __shared__ float t[32][33];
    int b  = blockIdx.z;
    int p0 = blockIdx.x * 32;
    int c0 = blockIdx.y * 32;
    int tx = threadIdx.x, ty = threadIdx.y;
    for (int i = ty; i < 32; i += 8)
        t[i][tx] = y[((size_t)b * P + p0 + i) * C + c0 + tx];
    __syncthreads();
    for (int i = ty; i < 32; i += 8)
        out[((size_t)b * C + c0 + i) * P + p0 + tx] = t[tx][i];
}

// =================================================================
// host launcher
// =================================================================
extern "C" void kernel_launch(void* const* d_in, const int* in_sizes, int n_in,
                              void* d_out, int out_size)
{
    const float* x       = (const float*)d_in[0];
    const float* conv_w  = (const float*)d_in[1];
    const float* conv_b  = (const float*)d_in[2];
    const float* norm1_w = (const float*)d_in[3];
    const float* norm1_b = (const float*)d_in[4];
    const float* wqkv    = (const float*)d_in[5];
    const float* proj_w  = (const float*)d_in[6];
    const float* proj_b  = (const float*)d_in[7];
    const float* norm2_w = (const float*)d_in[8];
    const float* norm2_b = (const float*)d_in[9];
    const float* fc1_w   = (const float*)d_in[10];
    const float* fc1_b   = (const float*)d_in[11];
    const float* fc2_w   = (const float*)d_in[12];
    const float* fc2_b   = (const float*)d_in[13];
    const float* ls1     = (const float*)d_in[14];
    const float* ls2     = (const float*)d_in[15];
    float* out = (float*)d_out;

    float *pxt, *pxn, *pqkv, *pabuf, *pxt2, *ph, *py;
    cudaGetSymbolAddress((void**)&pxt,   g_xt);
    cudaGetSymbolAddress((void**)&pxn,   g_xn);
    cudaGetSymbolAddress((void**)&pqkv,  g_qkv);
    cudaGetSymbolAddress((void**)&pabuf, g_abuf);
    cudaGetSymbolAddress((void**)&pxt2,  g_xt2);
    cudaGetSymbolAddress((void**)&ph,    g_h);
    cudaGetSymbolAddress((void**)&py,    g_y);

    // 1. conv + residual + transpose -> xt (B,P,C)
    conv_kernel<<<dim3(16, HH, BS), 256>>>(x, conv_w, conv_b, pxt);

    // 2. LN1 -> xn
    ln_kernel<<<(int)(M / 8), 256>>>(pxt, norm1_w, norm1_b, pxn);

    // 3. QKV GEMM: (M x 128) @ (128 x 384)
    {
        EpiQKV e{pqkv};
        sgemm_kernel<EpiQKV><<<dim3(384 / BN, (unsigned)(M / BM)), 256>>>(
            pxn, wqkv, 128, 384, e);
    }

    // 4. attention (both branches read qkv, write disjoint channel halves)
    win_attn_kernel<<<BS * 256, 256>>>(pqkv, pabuf);
    grid_attn_kernel<<<BS * 256, 256>>>(pqkv, pabuf);

    // 5. proj GEMM + ls1 + residual -> xt2
    {
        EpiProj e{proj_b, ls1, pxt, pxt2};
        sgemm_kernel<EpiProj><<<dim3(128 / BN, (unsigned)(M / BM)), 256>>>(
            pabuf, proj_w, 128, 128, e);
    }

    // 6. LN2 -> xn (reuse)
    ln_kernel<<<(int)(M / 8), 256>>>(pxt2, norm2_w, norm2_b, pxn);

    // 7. FC1 GEMM + bias + exact GELU -> h
    {
        EpiGelu e{fc1_b, ph};
        sgemm_kernel<EpiGelu><<<dim3(HID / BN, (unsigned)(M / BM)), 256>>>(
            pxn, fc1_w, 128, HID, e);
    }

    // 8. FC2 GEMM + bias + ls2 + residual -> y
    {
        EpiFc2 e{fc2_b, ls2, pxt2, py};
        sgemm_kernel<EpiFc2><<<dim3(128 / BN, (unsigned)(M / BM)), 256>>>(
            ph, fc2_w, 512, 128, e);
    }

    // 9. transpose -> d_out (B,C,H,W)
    transpose_out_kernel<<<dim3(P / 32, C / 32, BS), dim3(32, 8)>>>(py, out);

    (void)in_sizes; (void)n_in; (void)out_size;
}

// round 5
// speedup vs baseline: 1.6370x; 1.6370x over previous
#include <cuda_runtime.h>
#include <cuda_bf16.h>
#include <math.h>
#include <stdint.h>

typedef unsigned int u32;

// ---------------- problem constants ----------------
constexpr int BS  = 8;
constexpr int C   = 128;
constexpr int HH  = 128;
constexpr int WW  = 128;
constexpr int P   = HH * WW;
constexpr long long M = (long long)BS * P;  // 131072 rows
constexpr int HID = 512;

// ---------------- device scratch ----------------
__device__ float          g_xt  [(size_t)M * C];       // residual stream (fp32)
__device__ __nv_bfloat16  g_xn  [(size_t)M * C];       // LN output (bf16, GEMM A)
__device__ float          g_qkv [(size_t)M * 3 * C];   // qkv (fp32, attention reads)
__device__ __nv_bfloat16  g_abuf[(size_t)M * C];       // attention out (bf16, GEMM A)
__device__ float          g_xt2 [(size_t)M * C];       // residual after attn (fp32)
__device__ __nv_bfloat16  g_h   [(size_t)M * HID];     // gelu(fc1) (bf16, GEMM A)
__device__ float          g_y   [(size_t)M * C];       // final pre-transpose

// transposed bf16 weights [N][K]
__device__ __nv_bfloat16  g_wqkv_t[384 * 128];
__device__ __nv_bfloat16  g_proj_t[128 * 128];
__device__ __nv_bfloat16  g_fc1_t [512 * 128];
__device__ __nv_bfloat16  g_fc2_t [128 * 512];

// =================================================================
// weight transpose + bf16 convert: W[K][N] fp32 -> Wt[N][K] bf16
// =================================================================
__global__ void wt_kernel(const float* __restrict__ W, __nv_bfloat16* __restrict__ Wt,
                          int K, int N)
{
    __shared__ float t[32][33];
    int k0 = blockIdx.y * 32, n0 = blockIdx.x * 32;
    int tx = threadIdx.x, ty = threadIdx.y;
    for (int i = ty; i < 32; i += 8)
        t[i][tx] = W[(size_t)(k0 + i) * N + n0 + tx];
    __syncthreads();
    for (int i = ty; i < 32; i += 8)
        Wt[(size_t)(n0 + i) * K + k0 + tx] = __float2bfloat16(t[tx][i]);
}

// =================================================================
// Kernel 1: depthwise 3x3 conv + bias + residual -> xt (B,P,C) fp32
// =================================================================
__global__ __launch_bounds__(256) void conv_kernel(
    const float* __restrict__ x, const float* __restrict__ cw,
    const float* __restrict__ cb, float* __restrict__ xt)
{
    int b  = blockIdx.z;
    int h  = blockIdx.y;
    int c0 = (blockIdx.x >> 2) * 32;
    int w0 = (blockIdx.x & 3) * 32;
    __shared__ float sx[32][3][36];
    __shared__ float so[32][33];
    int tid = threadIdx.x;

    for (int i = tid; i < 32 * 3 * 34; i += 256) {
        int c  = i / (3 * 34);
        int r  = (i / 34) % 3;
        int wi = i % 34;
        int hh = h + r - 1;
        int wg = w0 + wi - 1;
        float v = 0.f;
        if (hh >= 0 && hh < HH && wg >= 0 && wg < WW)
            v = x[(((size_t)b * C + c0 + c) * HH + hh) * WW + wg];
        sx[c][r][wi] = v;
    }
    __syncthreads();

    int c     = tid >> 3;
    int wbase = (tid & 7) * 4;
    const float* wg9 = cw + (size_t)(c0 + c) * 9;
    float w00 = wg9[0], w01 = wg9[1], w02 = wg9[2];
    float w10 = wg9[3], w11 = wg9[4], w12 = wg9[5];
    float w20 = wg9[6], w21 = wg9[7], w22 = wg9[8];
    float bias = cb[c0 + c];
#pragma unroll
    for (int j = 0; j < 4; j++) {
        int wi = wbase + j;
        float acc = sx[c][0][wi] * w00 + sx[c][0][wi+1] * w01 + sx[c][0][wi+2] * w02
                  + sx[c][1][wi] * w10 + sx[c][1][wi+1] * w11 + sx[c][1][wi+2] * w12
                  + sx[c][2][wi] * w20 + sx[c][2][wi+1] * w21 + sx[c][2][wi+2] * w22;
        so[c][wi] = acc + bias + sx[c][1][wi+1];
    }
    __syncthreads();

    int cc = tid & 31;
    for (int wr = tid >> 5; wr < 32; wr += 8) {
        xt[((size_t)b * P + (size_t)h * WW + w0 + wr) * C + c0 + cc] = so[cc][wr];
    }
}

// =================================================================
// Kernel 2: LayerNorm over C=128, one warp per token, bf16 output
// =================================================================
__global__ __launch_bounds__(256) void ln_kernel(
    const float* __restrict__ in, const float* __restrict__ w,
    const float* __restrict__ b, __nv_bfloat16* __restrict__ out)
{
    size_t t  = (size_t)blockIdx.x * 8 + (threadIdx.x >> 5);
    int lane  = threadIdx.x & 31;
    const float4* row = (const float4*)(in + t * C);
    float4 v = row[lane];
    float s = v.x + v.y + v.z + v.w;
#pragma unroll
    for (int o = 16; o; o >>= 1) s += __shfl_xor_sync(0xffffffffu, s, o);
    float mean = s * (1.f / 128.f);
    float dx = v.x - mean, dy = v.y - mean, dz = v.z - mean, dw = v.w - mean;
    float vs = dx*dx + dy*dy + dz*dz + dw*dw;
#pragma unroll
    for (int o = 16; o; o >>= 1) vs += __shfl_xor_sync(0xffffffffu, vs, o);
    float rstd = rsqrtf(vs * (1.f / 128.f) + 1e-5f);
    float4 wv = ((const float4*)w)[lane];
    float4 bv = ((const float4*)b)[lane];
    __nv_bfloat162* ob = (__nv_bfloat162*)(out + t * C);
    ob[lane * 2 + 0] = __floats2bfloat162_rn(dx * rstd * wv.x + bv.x,
                                             dy * rstd * wv.y + bv.y);
    ob[lane * 2 + 1] = __floats2bfloat162_rn(dz * rstd * wv.z + bv.z,
                                             dw * rstd * wv.w + bv.w);
}

// =================================================================
// bf16 tensor-core GEMM: C[M,N] = A[M,K] @ Wt[N,K]^T
// CTA 128x128, BK=32, 8 warps (2x4), warp tile 64x32,
// mma.sync.m16n8k16.bf16, conflict-free padded ldmatrix.
// =================================================================
constexpr int BM = 128, BN = 128, BKg = 32;
constexpr int LDS_S = BKg + 8;   // 40 bf16 = 80B row stride (conflict-free)

__device__ __forceinline__ void ldsm_x4(u32 &r0, u32 &r1, u32 &r2, u32 &r3, u32 addr)
{
    asm volatile("ldmatrix.sync.aligned.m8n8.x4.shared.b16 {%0,%1,%2,%3}, [%4];"
                 : "=r"(r0), "=r"(r1), "=r"(r2), "=r"(r3) : "r"(addr));
}
__device__ __forceinline__ void mma_bf16(float* d, const u32* a, const u32* b)
{
    asm volatile("mma.sync.aligned.m16n8k16.row.col.f32.bf16.bf16.f32 "
                 "{%0,%1,%2,%3}, {%4,%5,%6,%7}, {%8,%9}, {%0,%1,%2,%3};"
                 : "+f"(d[0]), "+f"(d[1]), "+f"(d[2]), "+f"(d[3])
                 : "r"(a[0]), "r"(a[1]), "r"(a[2]), "r"(a[3]),
                   "r"(b[0]), "r"(b[1]));
}

struct EpiQKV {
    float* out;
    __device__ __forceinline__ void store(size_t row, int col, float2 v) const {
        *(float2*)(out + row * 384 + col) = v;
    }
};
struct EpiProj {   // xt2 = xt + ls1 * (v + bias)   (fp32 out)
    const float* bias; const float* ls; const float* resid; float* out;
    __device__ __forceinline__ void store(size_t row, int col, float2 v) const {
        float2 bb = *(const float2*)(bias + col);
        float2 ss = *(const float2*)(ls + col);
        float2 rr = *(const float2*)(resid + row * 128 + col);
        float2 o;
        o.x = rr.x + ss.x * (v.x + bb.x);
        o.y = rr.y + ss.y * (v.y + bb.y);
        *(float2*)(out + row * 128 + col) = o;
    }
};
struct EpiGelu {   // h = gelu(v + bias)  -> bf16, N=512
    const float* bias; __nv_bfloat16* out;
    __device__ __forceinline__ float gelu(float g) const {
        return 0.5f * g * (1.f + erff(g * 0.70710678118654752f));
    }
    __device__ __forceinline__ void store(size_t row, int col, float2 v) const {
        float2 bb = *(const float2*)(bias + col);
        *(__nv_bfloat162*)(out + row * 512 + col) =
            __floats2bfloat162_rn(gelu(v.x + bb.x), gelu(v.y + bb.y));
    }
};
struct EpiFc2 {    // y = xt2 + ls2 * (v + bias)   (fp32 out)
    const float* bias; const float* ls; const float* resid; float* out;
    __device__ __forceinline__ void store(size_t row, int col, float2 v) const {
        float2 bb = *(const float2*)(bias + col);
        float2 ss = *(const float2*)(ls + col);
        float2 rr = *(const float2*)(resid + row * 128 + col);
        float2 o;
        o.x = rr.x + ss.x * (v.x + bb.x);
        o.y = rr.y + ss.y * (v.y + bb.y);
        *(float2*)(out + row * 128 + col) = o;
    }
};

template <class Epi>
__global__ __launch_bounds__(256, 2) void bgemm_kernel(
    const __nv_bfloat16* __restrict__ A, const __nv_bfloat16* __restrict__ Bw,
    int K, Epi epi)
{
    __shared__ __nv_bfloat16 As[BM][LDS_S];
    __shared__ __nv_bfloat16 Bs[BN][LDS_S];
    int tid = threadIdx.x, lane = tid & 31, w = tid >> 5;
    int wm = w & 1, wn = w >> 1;
    size_t rowBase = (size_t)blockIdx.y * BM;
    int    colBase = blockIdx.x * BN;

    int ldRow = tid >> 1;
    int ldCol = (tid & 1) * 16;
    const __nv_bfloat16* Ap = A  + (rowBase + ldRow) * K + ldCol;
    const __nv_bfloat16* Bp = Bw + (size_t)(colBase + ldRow) * K + ldCol;

    float acc[4][4][4];
#pragma unroll
    for (int i = 0; i < 4; i++)
#pragma unroll
        for (int j = 0; j < 4; j++)
#pragma unroll
            for (int r = 0; r < 4; r++) acc[i][j][r] = 0.f;

    uint4 av0 = *(const uint4*)Ap, av1 = *(const uint4*)(Ap + 8);
    uint4 bv0 = *(const uint4*)Bp, bv1 = *(const uint4*)(Bp + 8);

    u32 sA = (u32)__cvta_generic_to_shared(&As[0][0]);
    u32 sB = (u32)__cvta_generic_to_shared(&Bs[0][0]);
    int arow = wm * 64 + (lane & 15);
    int brow = wn * 32 + (lane & 15);
    int csel = (lane >> 4) * 8;

    for (int kt = 0; kt < K; kt += BKg) {
        __syncthreads();
        *(uint4*)&As[ldRow][ldCol]     = av0;
        *(uint4*)&As[ldRow][ldCol + 8] = av1;
        *(uint4*)&Bs[ldRow][ldCol]     = bv0;
        *(uint4*)&Bs[ldRow][ldCol + 8] = bv1;
        if (kt + BKg < K) {
            Ap += BKg; Bp += BKg;
            av0 = *(const uint4*)Ap; av1 = *(const uint4*)(Ap + 8);
            bv0 = *(const uint4*)Bp; bv1 = *(const uint4*)(Bp + 8);
        }
        __syncthreads();
#pragma unroll
        for (int kk = 0; kk < BKg; kk += 16) {
            u32 af[4][4], bf[4][2];
            int acol = kk + csel;
#pragma unroll
            for (int mi = 0; mi < 4; mi++) {
                u32 addr = sA + (u32)(((arow + mi * 16) * LDS_S + acol) * 2);
                ldsm_x4(af[mi][0], af[mi][1], af[mi][2], af[mi][3], addr);
            }
#pragma unroll
            for (int np = 0; np < 2; np++) {
                u32 r0, r1, r2, r3;
                u32 addr = sB + (u32)(((brow + np * 16) * LDS_S + acol) * 2);
                ldsm_x4(r0, r1, r2, r3, addr);
                bf[np * 2][0]     = r0; bf[np * 2][1]     = r2;
                bf[np * 2 + 1][0] = r1; bf[np * 2 + 1][1] = r3;
            }
#pragma unroll
            for (int mi = 0; mi < 4; mi++)
#pragma unroll
                for (int nj = 0; nj < 4; nj++)
                    mma_bf16(acc[mi][nj], af[mi], bf[nj]);
        }
    }

#pragma unroll
    for (int mi = 0; mi < 4; mi++)
#pragma unroll
        for (int rp = 0; rp < 2; rp++) {
            size_t r = rowBase + wm * 64 + mi * 16 + rp * 8 + (lane >> 2);
#pragma unroll
            for (int nj = 0; nj < 4; nj++) {
                int cgl = colBase + wn * 32 + nj * 8 + (lane & 3) * 2;
                epi.store(r, cgl, make_float2(acc[mi][nj][rp * 2],
                                              acc[mi][nj][rp * 2 + 1]));
            }
        }
}

// =================================================================
// Window attention (heads 0..3, 64-token windows), bf16 out
// =================================================================
__global__ __launch_bounds__(256) void win_attn_kernel(
    const float* __restrict__ qkv, __nv_bfloat16* __restrict__ abuf)
{
    int blk = blockIdx.x;
    int b  = blk >> 8;
    int wy = (blk >> 4) & 15;
    int wx = blk & 15;
    int tid = threadIdx.x;
    int l = tid >> 6;
    int i = tid & 63;
    int y = i >> 3, x = i & 7;
    size_t p = (size_t)(wy * 8 + y) * WW + wx * 8 + x;
    const float* base = qkv + ((size_t)b * P + p) * 384;

    __shared__ float sk[4][64][16];
    __shared__ float sv[4][64][16];

    {
        const float4* kg = (const float4*)(base + 128 + l * 16);
        const float4* vg = (const float4*)(base + 256 + l * 16);
        float4* kd = (float4*)sk[l][i];
        float4* vd = (float4*)sv[l][i];
        kd[0] = kg[0]; kd[1] = kg[1]; kd[2] = kg[2]; kd[3] = kg[3];
        vd[0] = vg[0]; vd[1] = vg[1]; vd[2] = vg[2]; vd[3] = vg[3];
    }
    const float4* qg = (const float4*)(base + l * 16);
    float4 q0 = qg[0], q1 = qg[1], q2 = qg[2], q3 = qg[3];
    __syncthreads();

    float4 o0 = {0,0,0,0}, o1 = {0,0,0,0}, o2 = {0,0,0,0}, o3 = {0,0,0,0};
    float lsum = 0.f;
    const float scale = 0.25f;

    for (int j = 0; j < 64; j++) {
        const float4* kr = (const float4*)sk[l][j];
        float4 ka = kr[0], kb = kr[1], kc = kr[2], kd = kr[3];
        float s = q0.x*ka.x + q0.y*ka.y + q0.z*ka.z + q0.w*ka.w
                + q1.x*kb.x + q1.y*kb.y + q1.z*kb.z + q1.w*kb.w
                + q2.x*kc.x + q2.y*kc.y + q2.z*kc.z + q2.w*kc.w
                + q3.x*kd.x + q3.y*kd.y + q3.z*kd.z + q3.w*kd.w;
        float e = __expf(s * scale);
        lsum += e;
        const float4* vr = (const float4*)sv[l][j];
        float4 va = vr[0], vb = vr[1], vc = vr[2], vd = vr[3];
        o0.x += e*va.x; o0.y += e*va.y; o0.z += e*va.z; o0.w += e*va.w;
        o1.x += e*vb.x; o1.y += e*vb.y; o1.z += e*vb.z; o1.w += e*vb.w;
        o2.x += e*vc.x; o2.y += e*vc.y; o2.z += e*vc.z; o2.w += e*vc.w;
        o3.x += e*vd.x; o3.y += e*vd.y; o3.z += e*vd.z; o3.w += e*vd.w;
    }
    float inv = 1.f / lsum;
    __nv_bfloat162* ob = (__nv_bfloat162*)(abuf + ((size_t)b * P + p) * C + l * 16);
    ob[0] = __floats2bfloat162_rn(o0.x*inv, o0.y*inv);
    ob[1] = __floats2bfloat162_rn(o0.z*inv, o0.w*inv);
    ob[2] = __floats2bfloat162_rn(o1.x*inv, o1.y*inv);
    ob[3] = __floats2bfloat162_rn(o1.z*inv, o1.w*inv);
    ob[4] = __floats2bfloat162_rn(o2.x*inv, o2.y*inv);
    ob[5] = __floats2bfloat162_rn(o2.z*inv, o2.w*inv);
    ob[6] = __floats2bfloat162_rn(o3.x*inv, o3.y*inv);
    ob[7] = __floats2bfloat162_rn(o3.z*inv, o3.w*inv);
}

// =================================================================
// Grid attention (heads 4..7, 256-token grids), bf16 out
// =================================================================
__global__ __launch_bounds__(256) void grid_attn_kernel(
    const float* __restrict__ qkv, __nv_bfloat16* __restrict__ abuf)
{
    int blk = blockIdx.x;
    int b   = blk >> 8;
    int pos = (blk >> 2) & 63;
    int g   = blk & 3;
    int y = pos >> 3, x = pos & 7;
    int tid = threadIdx.x;
    int wy = tid >> 4, wx = tid & 15;
    size_t p = (size_t)(wy * 8 + y) * WW + wx * 8 + x;
    const float* base = qkv + ((size_t)b * P + p) * 384;
    int hc = (4 + g) * 16;

    __shared__ float sk[256][16];
    __shared__ float sv[256][16];

    {
        const float4* kg = (const float4*)(base + 128 + hc);
        const float4* vg = (const float4*)(base + 256 + hc);
        float4* kd = (float4*)sk[tid];
        float4* vd = (float4*)sv[tid];
        kd[0] = kg[0]; kd[1] = kg[1]; kd[2] = kg[2]; kd[3] = kg[3];
        vd[0] = vg[0]; vd[1] = vg[1]; vd[2] = vg[2]; vd[3] = vg[3];
    }
    const float4* qg = (const float4*)(base + hc);
    float4 q0 = qg[0], q1 = qg[1], q2 = qg[2], q3 = qg[3];
    __syncthreads();

    float4 o0 = {0,0,0,0}, o1 = {0,0,0,0}, o2 = {0,0,0,0}, o3 = {0,0,0,0};
    float lsum = 0.f;
    const float scale = 0.25f;

    for (int j = 0; j < 256; j++) {
        const float4* kr = (const float4*)sk[j];
        float4 ka = kr[0], kb = kr[1], kc = kr[2], kd = kr[3];
        float s = q0.x*ka.x + q0.y*ka.y + q0.z*ka.z + q0.w*ka.w
                + q1.x*kb.x + q1.y*kb.y + q1.z*kb.z + q1.w*kb.w
                + q2.x*kc.x + q2.y*kc.y + q2.z*kc.z + q2.w*kc.w
                + q3.x*kd.x + q3.y*kd.y + q3.z*kd.z + q3.w*kd.w;
        float e = __expf(s * scale);
        lsum += e;
        const float4* vr = (const float4*)sv[j];
        float4 va = vr[0], vb = vr[1], vc = vr[2], vd = vr[3];
        o0.x += e*va.x; o0.y += e*va.y; o0.z += e*va.z; o0.w += e*va.w;
        o1.x += e*vb.x; o1.y += e*vb.y; o1.z += e*vb.z; o1.w += e*vb.w;
        o2.x += e*vc.x; o2.y += e*vc.y; o2.z += e*vc.z; o2.w += e*vc.w;
        o3.x += e*vd.x; o3.y += e*vd.y; o3.z += e*vd.z; o3.w += e*vd.w;
    }
    float inv = 1.f / lsum;
    __nv_bfloat162* ob = (__nv_bfloat162*)(abuf + ((size_t)b * P + p) * C + 64 + g * 16);
    ob[0] = __floats2bfloat162_rn(o0.x*inv, o0.y*inv);
    ob[1] = __floats2bfloat162_rn(o0.z*inv, o0.w*inv);
    ob[2] = __floats2bfloat162_rn(o1.x*inv, o1.y*inv);
    ob[3] = __floats2bfloat162_rn(o1.z*inv, o1.w*inv);
    ob[4] = __floats2bfloat162_rn(o2.x*inv, o2.y*inv);
    ob[5] = __floats2bfloat162_rn(o2.z*inv, o2.w*inv);
    ob[6] = __floats2bfloat162_rn(o3.x*inv, o3.y*inv);
    ob[7] = __floats2bfloat162_rn(o3.z*inv, o3.w*inv);
}

// =================================================================
// Final transpose: (B, P, C) -> (B, C, P)
// =================================================================
__global__ void transpose_out_kernel(const float* __restrict__ y,
                                     float* __restrict__ out)
{
    __shared__ float t[32][33];
    int b  = blockIdx.z;
    int p0 = blockIdx.x * 32;
    int c0 = blockIdx.y * 32;
    int tx = threadIdx.x, ty = threadIdx.y;
    for (int i = ty; i < 32; i += 8)
        t[i][tx] = y[((size_t)b * P + p0 + i) * C + c0 + tx];
    __syncthreads();
    for (int i = ty; i < 32; i += 8)
        out[((size_t)b * C + c0 + i) * P + p0 + tx] = t[tx][i];
}

// =================================================================
// host launcher
// =================================================================
extern "C" void kernel_launch(void* const* d_in, const int* in_sizes, int n_in,
                              void* d_out, int out_size)
{
    const float* x       = (const float*)d_in[0];
    const float* conv_w  = (const float*)d_in[1];
    const float* conv_b  = (const float*)d_in[2];
    const float* norm1_w = (const float*)d_in[3];
    const float* norm1_b = (const float*)d_in[4];
    const float* wqkv    = (const float*)d_in[5];
    const float* proj_w  = (const float*)d_in[6];
    const float* proj_b  = (const float*)d_in[7];
    const float* norm2_w = (const float*)d_in[8];
    const float* norm2_b = (const float*)d_in[9];
    const float* fc1_w   = (const float*)d_in[10];
    const float* fc1_b   = (const float*)d_in[11];
    const float* fc2_w   = (const float*)d_in[12];
    const float* fc2_b   = (const float*)d_in[13];
    const float* ls1     = (const float*)d_in[14];
    const float* ls2     = (const float*)d_in[15];
    float* out = (float*)d_out;

    float *pxt, *pqkv, *pxt2, *py;
    __nv_bfloat16 *pxn, *pabuf, *ph, *pwq, *pwp, *pw1, *pw2;
    cudaGetSymbolAddress((void**)&pxt,   g_xt);
    cudaGetSymbolAddress((void**)&pxn,   g_xn);
    cudaGetSymbolAddress((void**)&pqkv,  g_qkv);
    cudaGetSymbolAddress((void**)&pabuf, g_abuf);
    cudaGetSymbolAddress((void**)&pxt2,  g_xt2);
    cudaGetSymbolAddress((void**)&ph,    g_h);
    cudaGetSymbolAddress((void**)&py,    g_y);
    cudaGetSymbolAddress((void**)&pwq,   g_wqkv_t);
    cudaGetSymbolAddress((void**)&pwp,   g_proj_t);
    cudaGetSymbolAddress((void**)&pw1,   g_fc1_t);
    cudaGetSymbolAddress((void**)&pw2,   g_fc2_t);

    // 0. weight transpose/convert (tiny)
    wt_kernel<<<dim3(384/32, 128/32), dim3(32, 8)>>>(wqkv,   pwq, 128, 384);
    wt_kernel<<<dim3(128/32, 128/32), dim3(32, 8)>>>(proj_w, pwp, 128, 128);
    wt_kernel<<<dim3(512/32, 128/32), dim3(32, 8)>>>(fc1_w,  pw1, 128, 512);
    wt_kernel<<<dim3(128/32, 512/32), dim3(32, 8)>>>(fc2_w,  pw2, 512, 128);

    // 1. conv + residual + transpose -> xt (fp32)
    conv_kernel<<<dim3(16, HH, BS), 256>>>(x, conv_w, conv_b, pxt);

    // 2. LN1 -> xn (bf16)
    ln_kernel<<<(int)(M / 8), 256>>>(pxt, norm1_w, norm1_b, pxn);

    // 3. QKV GEMM (M x 128) @ (128 x 384) -> fp32 qkv
    {
        EpiQKV e{pqkv};
        bgemm_kernel<EpiQKV><<<dim3(3, (unsigned)(M / BM)), 256>>>(pxn, pwq, 128, e);
    }

    // 4. attention -> abuf (bf16)
    win_attn_kernel <<<BS * 256, 256>>>(pqkv, pabuf);
    grid_attn_kernel<<<BS * 256, 256>>>(pqkv, pabuf);

    // 5. proj GEMM + ls1 + residual -> xt2 (fp32)
    {
        EpiProj e{proj_b, ls1, pxt, pxt2};
        bgemm_kernel<EpiProj><<<dim3(1, (unsigned)(M / BM)), 256>>>(pabuf, pwp, 128, e);
    }

    // 6. LN2 -> xn (bf16)
    ln_kernel<<<(int)(M / 8), 256>>>(pxt2, norm2_w, norm2_b, pxn);

    // 7. FC1 + bias + GELU -> h (bf16)
    {
        EpiGelu e{fc1_b, ph};
        bgemm_kernel<EpiGelu><<<dim3(4, (unsigned)(M / BM)), 256>>>(pxn, pw1, 128, e);
    }

    // 8. FC2 + bias + ls2 + residual -> y (fp32)
    {
        EpiFc2 e{fc2_b, ls2, pxt2, py};
        bgemm_kernel<EpiFc2><<<dim3(1, (unsigned)(M / BM)), 256>>>(ph, pw2, 512, e);
    }

    // 9. transpose -> d_out
    transpose_out_kernel<<<dim3(P / 32, C / 32, BS), dim3(32, 8)>>>(py, out);

    (void)in_sizes; (void)n_in; (void)out_size;
}

// round 7
// speedup vs baseline: 2.4567x; 1.5008x over previous
#include <cuda_runtime.h>
#include <cuda_bf16.h>
#include <math.h>
#include <stdint.h>
#include <string.h>

typedef unsigned int u32;

// ---------------- problem constants ----------------
constexpr int BS  = 8;
constexpr int C   = 128;
constexpr int HH  = 128;
constexpr int WW  = 128;
constexpr int P   = HH * WW;
constexpr long long M = (long long)BS * P;  // 131072 rows
constexpr int HID = 512;

// ---------------- device scratch ----------------
__device__ float          g_xt  [(size_t)M * C];       // residual stream (fp32)
__device__ __nv_bfloat16  g_xn  [(size_t)M * C];       // LN output (bf16)
__device__ __nv_bfloat16  g_qkvb[(size_t)M * 3 * C];   // qkv (bf16)
__device__ __nv_bfloat16  g_abuf[(size_t)M * C];       // attention out (bf16)
__device__ float          g_xt2 [(size_t)M * C];       // residual after attn (fp32)
__device__ __nv_bfloat16  g_h   [(size_t)M * HID];     // gelu(fc1) (bf16)
__device__ float          g_y   [(size_t)M * C];       // final pre-transpose

// transposed bf16 weights [N][K]
__device__ __nv_bfloat16  g_wqkv_t[384 * 128];
__device__ __nv_bfloat16  g_proj_t[128 * 128];
__device__ __nv_bfloat16  g_fc1_t [512 * 128];
__device__ __nv_bfloat16  g_fc2_t [128 * 512];

// =================================================================
// mma / ldmatrix primitives
// =================================================================
__device__ __forceinline__ void ldsm_x4(u32 &r0, u32 &r1, u32 &r2, u32 &r3, u32 addr)
{
    asm volatile("ldmatrix.sync.aligned.m8n8.x4.shared.b16 {%0,%1,%2,%3}, [%4];"
                 : "=r"(r0), "=r"(r1), "=r"(r2), "=r"(r3) : "r"(addr));
}
__device__ __forceinline__ void ldsm_x4_t(u32 &r0, u32 &r1, u32 &r2, u32 &r3, u32 addr)
{
    asm volatile("ldmatrix.sync.aligned.m8n8.x4.trans.shared.b16 {%0,%1,%2,%3}, [%4];"
                 : "=r"(r0), "=r"(r1), "=r"(r2), "=r"(r3) : "r"(addr));
}
__device__ __forceinline__ void mma_bf16(float* d, const u32* a, const u32* b)
{
    asm volatile("mma.sync.aligned.m16n8k16.row.col.f32.bf16.bf16.f32 "
                 "{%0,%1,%2,%3}, {%4,%5,%6,%7}, {%8,%9}, {%0,%1,%2,%3};"
                 : "+f"(d[0]), "+f"(d[1]), "+f"(d[2]), "+f"(d[3])
                 : "r"(a[0]), "r"(a[1]), "r"(a[2]), "r"(a[3]),
                   "r"(b[0]), "r"(b[1]));
}
__device__ __forceinline__ u32 pack_bf16x2(float a, float b)
{
    __nv_bfloat162 t = __floats2bfloat162_rn(a, b);
    u32 r;
    memcpy(&r, &t, 4);
    return r;
}

// =================================================================
// weight transpose + bf16 convert: W[K][N] fp32 -> Wt[N][K] bf16
// =================================================================
__global__ void wt_kernel(const float* __restrict__ W, __nv_bfloat16* __restrict__ Wt,
                          int K, int N)
{
    __shared__ float t[32][33];
    int k0 = blockIdx.y * 32, n0 = blockIdx.x * 32;
    int tx = threadIdx.x, ty = threadIdx.y;
    for (int i = ty; i < 32; i += 8)
        t[i][tx] = W[(size_t)(k0 + i) * N + n0 + tx];
    __syncthreads();
    for (int i = ty; i < 32; i += 8)
        Wt[(size_t)(n0 + i) * K + k0 + tx] = __float2bfloat16(t[tx][i]);
}

// =================================================================
// Kernel 1: depthwise 3x3 conv + bias + residual -> xt (B,P,C) fp32
// =================================================================
__global__ __launch_bounds__(256) void conv_kernel(
    const float* __restrict__ x, const float* __restrict__ cw,
    const float* __restrict__ cb, float* __restrict__ xt)
{
    int b  = blockIdx.z;
    int h  = blockIdx.y;
    int c0 = (blockIdx.x >> 2) * 32;
    int w0 = (blockIdx.x & 3) * 32;
    __shared__ float sx[32][3][36];
    __shared__ float so[32][33];
    int tid = threadIdx.x;

    for (int i = tid; i < 32 * 3 * 34; i += 256) {
        int c  = i / (3 * 34);
        int r  = (i / 34) % 3;
        int wi = i % 34;
        int hh = h + r - 1;
        int wg = w0 + wi - 1;
        float v = 0.f;
        if (hh >= 0 && hh < HH && wg >= 0 && wg < WW)
            v = x[(((size_t)b * C + c0 + c) * HH + hh) * WW + wg];
        sx[c][r][wi] = v;
    }
    __syncthreads();

    int c     = tid >> 3;
    int wbase = (tid & 7) * 4;
    const float* wg9 = cw + (size_t)(c0 + c) * 9;
    float w00 = wg9[0], w01 = wg9[1], w02 = wg9[2];
    float w10 = wg9[3], w11 = wg9[4], w12 = wg9[5];
    float w20 = wg9[6], w21 = wg9[7], w22 = wg9[8];
    float bias = cb[c0 + c];
#pragma unroll
    for (int j = 0; j < 4; j++) {
        int wi = wbase + j;
        float acc = sx[c][0][wi] * w00 + sx[c][0][wi+1] * w01 + sx[c][0][wi+2] * w02
                  + sx[c][1][wi] * w10 + sx[c][1][wi+1] * w11 + sx[c][1][wi+2] * w12
                  + sx[c][2][wi] * w20 + sx[c][2][wi+1] * w21 + sx[c][2][wi+2] * w22;
        so[c][wi] = acc + bias + sx[c][1][wi+1];
    }
    __syncthreads();

    int cc = tid & 31;
    for (int wr = tid >> 5; wr < 32; wr += 8) {
        xt[((size_t)b * P + (size_t)h * WW + w0 + wr) * C + c0 + cc] = so[cc][wr];
    }
}

// =================================================================
// Kernel 2: LayerNorm over C=128, one warp per token, bf16 output
// =================================================================
__global__ __launch_bounds__(256) void ln_kernel(
    const float* __restrict__ in, const float* __restrict__ w,
    const float* __restrict__ b, __nv_bfloat16* __restrict__ out)
{
    size_t t  = (size_t)blockIdx.x * 8 + (threadIdx.x >> 5);
    int lane  = threadIdx.x & 31;
    const float4* row = (const float4*)(in + t * C);
    float4 v = row[lane];
    float s = v.x + v.y + v.z + v.w;
#pragma unroll
    for (int o = 16; o; o >>= 1) s += __shfl_xor_sync(0xffffffffu, s, o);
    float mean = s * (1.f / 128.f);
    float dx = v.x - mean, dy = v.y - mean, dz = v.z - mean, dw = v.w - mean;
    float vs = dx*dx + dy*dy + dz*dz + dw*dw;
#pragma unroll
    for (int o = 16; o; o >>= 1) vs += __shfl_xor_sync(0xffffffffu, vs, o);
    float rstd = rsqrtf(vs * (1.f / 128.f) + 1e-5f);
    float4 wv = ((const float4*)w)[lane];
    float4 bv = ((const float4*)b)[lane];
    __nv_bfloat162* ob = (__nv_bfloat162*)(out + t * C);
    ob[lane * 2 + 0] = __floats2bfloat162_rn(dx * rstd * wv.x + bv.x,
                                             dy * rstd * wv.y + bv.y);
    ob[lane * 2 + 1] = __floats2bfloat162_rn(dz * rstd * wv.z + bv.z,
                                             dw * rstd * wv.w + bv.w);
}

// =================================================================
// bf16 tensor-core GEMM: CTA 128x128, BK=32, 8 warps.
// =================================================================
constexpr int BM = 128, BN = 128, BKg = 32;
constexpr int LDS_S = BKg + 8;

struct EpiQKVb {   // qkv -> bf16
    __nv_bfloat16* out;
    __device__ __forceinline__ void store(size_t row, int col, float2 v) const {
        *(__nv_bfloat162*)(out + row * 384 + col) = __floats2bfloat162_rn(v.x, v.y);
    }
};
struct EpiProj {   // xt2 = xt + ls1 * (v + bias)   (fp32 out)
    const float* bias; const float* ls; const float* resid; float* out;
    __device__ __forceinline__ void store(size_t row, int col, float2 v) const {
        float2 bb = *(const float2*)(bias + col);
        float2 ss = *(const float2*)(ls + col);
        float2 rr = *(const float2*)(resid + row * 128 + col);
        float2 o;
        o.x = rr.x + ss.x * (v.x + bb.x);
        o.y = rr.y + ss.y * (v.y + bb.y);
        *(float2*)(out + row * 128 + col) = o;
    }
};
struct EpiGelu {   // h = gelu(v + bias)  -> bf16, N=512
    const float* bias; __nv_bfloat16* out;
    __device__ __forceinline__ float gelu(float g) const {
        return 0.5f * g * (1.f + erff(g * 0.70710678118654752f));
    }
    __device__ __forceinline__ void store(size_t row, int col, float2 v) const {
        float2 bb = *(const float2*)(bias + col);
        *(__nv_bfloat162*)(out + row * 512 + col) =
            __floats2bfloat162_rn(gelu(v.x + bb.x), gelu(v.y + bb.y));
    }
};
struct EpiFc2 {    // y = xt2 + ls2 * (v + bias)   (fp32 out)
    const float* bias; const float* ls; const float* resid; float* out;
    __device__ __forceinline__ void store(size_t row, int col, float2 v) const {
        float2 bb = *(const float2*)(bias + col);
        float2 ss = *(const float2*)(ls + col);
        float2 rr = *(const float2*)(resid + row * 128 + col);
        float2 o;
        o.x = rr.x + ss.x * (v.x + bb.x);
        o.y = rr.y + ss.y * (v.y + bb.y);
        *(float2*)(out + row * 128 + col) = o;
    }
};

template <class Epi>
__global__ __launch_bounds__(256, 2) void bgemm_kernel(
    const __nv_bfloat16* __restrict__ A, const __nv_bfloat16* __restrict__ Bw,
    int K, Epi epi)
{
    __shared__ __nv_bfloat16 As[BM][LDS_S];
    __shared__ __nv_bfloat16 Bs[BN][LDS_S];
    int tid = threadIdx.x, lane = tid & 31, w = tid >> 5;
    int wm = w & 1, wn = w >> 1;
    size_t rowBase = (size_t)blockIdx.y * BM;
    int    colBase = blockIdx.x * BN;

    int ldRow = tid >> 1;
    int ldCol = (tid & 1) * 16;
    const __nv_bfloat16* Ap = A  + (rowBase + ldRow) * K + ldCol;
    const __nv_bfloat16* Bp = Bw + (size_t)(colBase + ldRow) * K + ldCol;

    float acc[4][4][4];
#pragma unroll
    for (int i = 0; i < 4; i++)
#pragma unroll
        for (int j = 0; j < 4; j++)
#pragma unroll
            for (int r = 0; r < 4; r++) acc[i][j][r] = 0.f;

    uint4 av0 = *(const uint4*)Ap, av1 = *(const uint4*)(Ap + 8);
    uint4 bv0 = *(const uint4*)Bp, bv1 = *(const uint4*)(Bp + 8);

    u32 sA = (u32)__cvta_generic_to_shared(&As[0][0]);
    u32 sB = (u32)__cvta_generic_to_shared(&Bs[0][0]);
    int arow = wm * 64 + (lane & 15);
    int brow = wn * 32 + (lane & 15);
    int csel = (lane >> 4) * 8;

    for (int kt = 0; kt < K; kt += BKg) {
        __syncthreads();
        *(uint4*)&As[ldRow][ldCol]     = av0;
        *(uint4*)&As[ldRow][ldCol + 8] = av1;
        *(uint4*)&Bs[ldRow][ldCol]     = bv0;
        *(uint4*)&Bs[ldRow][ldCol + 8] = bv1;
        if (kt + BKg < K) {
            Ap += BKg; Bp += BKg;
            av0 = *(const uint4*)Ap; av1 = *(const uint4*)(Ap + 8);
            bv0 = *(const uint4*)Bp; bv1 = *(const uint4*)(Bp + 8);
        }
        __syncthreads();
#pragma unroll
        for (int kk = 0; kk < BKg; kk += 16) {
            u32 af[4][4], bf[4][2];
            int acol = kk + csel;
#pragma unroll
            for (int mi = 0; mi < 4; mi++) {
                u32 addr = sA + (u32)(((arow + mi * 16) * LDS_S + acol) * 2);
                ldsm_x4(af[mi][0], af[mi][1], af[mi][2], af[mi][3], addr);
            }
#pragma unroll
            for (int np = 0; np < 2; np++) {
                u32 r0, r1, r2, r3;
                u32 addr = sB + (u32)(((brow + np * 16) * LDS_S + acol) * 2);
                ldsm_x4(r0, r1, r2, r3, addr);
                bf[np * 2][0]     = r0; bf[np * 2][1]     = r2;
                bf[np * 2 + 1][0] = r1; bf[np * 2 + 1][1] = r3;
            }
#pragma unroll
            for (int mi = 0; mi < 4; mi++)
#pragma unroll
                for (int nj = 0; nj < 4; nj++)
                    mma_bf16(acc[mi][nj], af[mi], bf[nj]);
        }
    }

#pragma unroll
    for (int mi = 0; mi < 4; mi++)
#pragma unroll
        for (int rp = 0; rp < 2; rp++) {
            size_t r = rowBase + wm * 64 + mi * 16 + rp * 8 + (lane >> 2);
#pragma unroll
            for (int nj = 0; nj < 4; nj++) {
                int cgl = colBase + wn * 32 + nj * 8 + (lane & 3) * 2;
                epi.store(r, cgl, make_float2(acc[mi][nj][rp * 2],
                                              acc[mi][nj][rp * 2 + 1]));
            }
        }
}

// =================================================================
// Warp-level attention core: 32 queries x (nchunks*64) keys, hd=16.
// Qs/Ks/Vs: smem, row stride 24 bf16 (conflict-free).
// Single-pass exp (no max shift; scores O(1)).
// o[2][2][4], rsum[2][2] returned un-normalized.
// =================================================================
constexpr int AST = 24;   // attention smem row stride (bf16)

__device__ __forceinline__ void attn_warp(
    const __nv_bfloat16* Qs, const __nv_bfloat16* Ks, const __nv_bfloat16* Vs,
    int nchunks, int lane, float o[2][2][4], float rsum[2][2])
{
    const float scale = 0.25f;
    int g = lane >> 3, i = lane & 7;
    int r4 = lane >> 2, c4 = lane & 3;

    // Q fragments for the warp's 32 rows (2 m-tiles of 16)
    u32 aq[2][4];
#pragma unroll
    for (int mt = 0; mt < 2; mt++) {
        u32 addr = (u32)__cvta_generic_to_shared(
            Qs + (mt * 16 + (g & 1) * 8 + i) * AST + (g >> 1) * 8);
        ldsm_x4(aq[mt][0], aq[mt][1], aq[mt][2], aq[mt][3], addr);
    }

#pragma unroll
    for (int mt = 0; mt < 2; mt++)
#pragma unroll
        for (int nh = 0; nh < 2; nh++)
#pragma unroll
            for (int q = 0; q < 4; q++) o[mt][nh][q] = 0.f;
    rsum[0][0] = rsum[0][1] = rsum[1][0] = rsum[1][1] = 0.f;

    for (int ch = 0; ch < nchunks; ch++) {
        const __nv_bfloat16* Kc = Ks + ch * 64 * AST;
        const __nv_bfloat16* Vc = Vs + ch * 64 * AST;
        u32 pf[2][4][4];   // P fragments: [m-tile][k-tile(16 tokens)][a-regs]
#pragma unroll
        for (int nt = 0; nt < 8; nt++) {
            const __nv_bfloat16* kp = Kc + (nt * 8 + r4) * AST + c4 * 2;
            u32 bb[2];
            bb[0] = *(const u32*)kp;
            bb[1] = *(const u32*)(kp + 8);
            float s0[4] = {0.f, 0.f, 0.f, 0.f};
            float s1[4] = {0.f, 0.f, 0.f, 0.f};
            mma_bf16(s0, aq[0], bb);
            mma_bf16(s1, aq[1], bb);
            float e00 = __expf(s0[0] * scale), e01 = __expf(s0[1] * scale);
            float e02 = __expf(s0[2] * scale), e03 = __expf(s0[3] * scale);
            float e10 = __expf(s1[0] * scale), e11 = __expf(s1[1] * scale);
            float e12 = __expf(s1[2] * scale), e13 = __expf(s1[3] * scale);
            rsum[0][0] += e00 + e01;  rsum[0][1] += e02 + e03;
            rsum[1][0] += e10 + e11;  rsum[1][1] += e12 + e13;
            int kt = nt >> 1, lo = (nt & 1) * 2;
            pf[0][kt][lo + 0] = pack_bf16x2(e00, e01);
            pf[0][kt][lo + 1] = pack_bf16x2(e02, e03);
            pf[1][kt][lo + 0] = pack_bf16x2(e10, e11);
            pf[1][kt][lo + 1] = pack_bf16x2(e12, e13);
        }
#pragma unroll
        for (int kt = 0; kt < 4; kt++) {
            u32 v0, v1, v2, v3;
            u32 addr = (u32)__cvta_generic_to_shared(
                Vc + (kt * 16 + (g & 1) * 8 + i) * AST + (g >> 1) * 8);
            ldsm_x4_t(v0, v1, v2, v3, addr);
            u32 b0[2] = {v0, v1};   // hd cols 0-7
            u32 b1[2] = {v2, v3};   // hd cols 8-15
            mma_bf16(o[0][0], pf[0][kt], b0);
            mma_bf16(o[0][1], pf[0][kt], b1);
            mma_bf16(o[1][0], pf[1][kt], b0);
            mma_bf16(o[1][1], pf[1][kt], b1);
        }
    }

    // reduce row sums across the 4 lanes of each quad
#pragma unroll
    for (int mt = 0; mt < 2; mt++)
#pragma unroll
        for (int hh = 0; hh < 2; hh++) {
            float v = rsum[mt][hh];
            v += __shfl_xor_sync(0xffffffffu, v, 1);
            v += __shfl_xor_sync(0xffffffffu, v, 2);
            rsum[mt][hh] = v;
        }
}

// =================================================================
// Window attention: CTA per (b, wy, wx); 4 heads x 2 warps.
// =================================================================
__global__ __launch_bounds__(256) void win_attn_kernel(
    const __nv_bfloat16* __restrict__ qkv, __nv_bfloat16* __restrict__ abuf)
{
    __shared__ __align__(16) __nv_bfloat16 Qs[4 * 64 * AST];
    __shared__ __align__(16) __nv_bfloat16 Ks[4 * 64 * AST];
    __shared__ __align__(16) __nv_bfloat16 Vs[4 * 64 * AST];

    int blk = blockIdx.x;
    int b  = blk >> 8;
    int wy = (blk >> 4) & 15;
    int wx = blk & 15;
    int tid = threadIdx.x;

    {   // stage: thread -> (head, token)
        int h = tid >> 6, t = tid & 63;
        int y = t >> 3, x = t & 7;
        size_t p = (size_t)(wy * 8 + y) * WW + wx * 8 + x;
        const __nv_bfloat16* base = qkv + ((size_t)b * P + p) * 384 + h * 16;
        int row = (h * 64 + t) * AST;
        const uint4* q4 = (const uint4*)base;
        const uint4* k4 = (const uint4*)(base + 128);
        const uint4* v4 = (const uint4*)(base + 256);
        *(uint4*)&Qs[row] = q4[0];  *(uint4*)&Qs[row + 8] = q4[1];
        *(uint4*)&Ks[row] = k4[0];  *(uint4*)&Ks[row + 8] = k4[1];
        *(uint4*)&Vs[row] = v4[0];  *(uint4*)&Vs[row + 8] = v4[1];
    }
    __syncthreads();

    int w = tid >> 5, lane = tid & 31;
    int h = w >> 1;
    int qb = (w & 1) * 32;

    float o[2][2][4], rsum[2][2];
    attn_warp(Qs + (h * 64 + qb) * AST, Ks + h * 64 * AST, Vs + h * 64 * AST,
              1, lane, o, rsum);

    int r4 = lane >> 2, c4 = lane & 3;
#pragma unroll
    for (int mt = 0; mt < 2; mt++) {
        float inv0 = 1.f / rsum[mt][0];
        float inv1 = 1.f / rsum[mt][1];
#pragma unroll
        for (int hh = 0; hh < 2; hh++) {
            int q = qb + mt * 16 + hh * 8 + r4;
            size_t p = (size_t)(wy * 8 + (q >> 3)) * WW + wx * 8 + (q & 7);
            float inv = hh ? inv1 : inv0;
            __nv_bfloat16* ob = abuf + ((size_t)b * P + p) * C + h * 16;
#pragma unroll
            for (int nh = 0; nh < 2; nh++) {
                float ox = o[mt][nh][hh * 2]     * inv;
                float oy = o[mt][nh][hh * 2 + 1] * inv;
                *(__nv_bfloat162*)(ob + nh * 8 + c4 * 2) = __floats2bfloat162_rn(ox, oy);
            }
        }
    }
}

// =================================================================
// Grid attention: CTA per (b, pos-in-window, head); 8 warps x 32 q.
// =================================================================
__global__ __launch_bounds__(256) void grid_attn_kernel(
    const __nv_bfloat16* __restrict__ qkv, __nv_bfloat16* __restrict__ abuf)
{
    __shared__ __align__(16) __nv_bfloat16 Qs[256 * AST];
    __shared__ __align__(16) __nv_bfloat16 Ks[256 * AST];
    __shared__ __align__(16) __nv_bfloat16 Vs[256 * AST];

    int blk = blockIdx.x;
    int b   = blk >> 8;
    int pos = (blk >> 2) & 63;
    int hg  = blk & 3;              // local head of global group (channels 64+hg*16)
    int y = pos >> 3, x = pos & 7;
    int tid = threadIdx.x;

    {   // stage: thread -> grid token j
        int j = tid;
        int wy = j >> 4, wx = j & 15;
        size_t p = (size_t)(wy * 8 + y) * WW + wx * 8 + x;
        const __nv_bfloat16* base = qkv + ((size_t)b * P + p) * 384 + 64 + hg * 16;
        int row = j * AST;
        const uint4* q4 = (const uint4*)base;
        const uint4* k4 = (const uint4*)(base + 128);
        const uint4* v4 = (const uint4*)(base + 256);
        *(uint4*)&Qs[row] = q4[0];  *(uint4*)&Qs[row + 8] = q4[1];
        *(uint4*)&Ks[row] = k4[0];  *(uint4*)&Ks[row + 8] = k4[1];
        *(uint4*)&Vs[row] = v4[0];  *(uint4*)&Vs[row + 8] = v4[1];
    }
    __syncthreads();

    int w = tid >> 5, lane = tid & 31;
    int qb = w * 32;

    float o[2][2][4], rsum[2][2];
    attn_warp(Qs + qb * AST, Ks, Vs, 4, lane, o, rsum);

    int r4 = lane >> 2, c4 = lane & 3;
#pragma unroll
    for (int mt = 0; mt < 2; mt++) {
        float inv0 = 1.f / rsum[mt][0];
        float inv1 = 1.f / rsum[mt][1];
#pragma unroll
        for (int hh = 0; hh < 2; hh++) {
            int j = qb + mt * 16 + hh * 8 + r4;
            int wy = j >> 4, wx = j & 15;
            size_t p = (size_t)(wy * 8 + y) * WW + wx * 8 + x;
            float inv = hh ? inv1 : inv0;
            __nv_bfloat16* ob = abuf + ((size_t)b * P + p) * C + 64 + hg * 16;
#pragma unroll
            for (int nh = 0; nh < 2; nh++) {
                float ox = o[mt][nh][hh * 2]     * inv;
                float oy = o[mt][nh][hh * 2 + 1] * inv;
                *(__nv_bfloat162*)(ob + nh * 8 + c4 * 2) = __floats2bfloat162_rn(ox, oy);
            }
        }
    }
}

// =================================================================
// Final transpose: (B, P, C) -> (B, C, P)
// =================================================================
__global__ void transpose_out_kernel(const float* __restrict__ y,
                                     float* __restrict__ out)
{
    __shared__ float t[32][33];
    int b  = blockIdx.z;
    int p0 = blockIdx.x * 32;
    int c0 = blockIdx.y * 32;
    int tx = threadIdx.x, ty = threadIdx.y;
    for (int i = ty; i < 32; i += 8)
        t[i][tx] = y[((size_t)b * P + p0 + i) * C + c0 + tx];
    __syncthreads();
    for (int i = ty; i < 32; i += 8)
        out[((size_t)b * C + c0 + i) * P + p0 + tx] = t[tx][i];
}

// =================================================================
// host launcher
// =================================================================
extern "C" void kernel_launch(void* const* d_in, const int* in_sizes, int n_in,
                              void* d_out, int out_size)
{
    const float* x       = (const float*)d_in[0];
    const float* conv_w  = (const float*)d_in[1];
    const float* conv_b  = (const float*)d_in[2];
    const float* norm1_w = (const float*)d_in[3];
    const float* norm1_b = (const float*)d_in[4];
    const float* wqkv    = (const float*)d_in[5];
    const float* proj_w  = (const float*)d_in[6];
    const float* proj_b  = (const float*)d_in[7];
    const float* norm2_w = (const float*)d_in[8];
    const float* norm2_b = (const float*)d_in[9];
    const float* fc1_w   = (const float*)d_in[10];
    const float* fc1_b   = (const float*)d_in[11];
    const float* fc2_w   = (const float*)d_in[12];
    const float* fc2_b   = (const float*)d_in[13];
    const float* ls1     = (const float*)d_in[14];
    const float* ls2     = (const float*)d_in[15];
    float* out = (float*)d_out;

    float *pxt, *pxt2, *py;
    __nv_bfloat16 *pxn, *pqkv, *pabuf, *ph, *pwq, *pwp, *pw1, *pw2;
    cudaGetSymbolAddress((void**)&pxt,   g_xt);
    cudaGetSymbolAddress((void**)&pxn,   g_xn);
    cudaGetSymbolAddress((void**)&pqkv,  g_qkvb);
    cudaGetSymbolAddress((void**)&pabuf, g_abuf);
    cudaGetSymbolAddress((void**)&pxt2,  g_xt2);
    cudaGetSymbolAddress((void**)&ph,    g_h);
    cudaGetSymbolAddress((void**)&py,    g_y);
    cudaGetSymbolAddress((void**)&pwq,   g_wqkv_t);
    cudaGetSymbolAddress((void**)&pwp,   g_proj_t);
    cudaGetSymbolAddress((void**)&pw1,   g_fc1_t);
    cudaGetSymbolAddress((void**)&pw2,   g_fc2_t);

    // 0. weight transpose/convert (tiny)
    wt_kernel<<<dim3(384/32, 128/32), dim3(32, 8)>>>(wqkv,   pwq, 128, 384);
    wt_kernel<<<dim3(128/32, 128/32), dim3(32, 8)>>>(proj_w, pwp, 128, 128);
    wt_kernel<<<dim3(512/32, 128/32), dim3(32, 8)>>>(fc1_w,  pw1, 128, 512);
    wt_kernel<<<dim3(128/32, 512/32), dim3(32, 8)>>>(fc2_w,  pw2, 512, 128);

    // 1. conv + residual + transpose -> xt (fp32)
    conv_kernel<<<dim3(16, HH, BS), 256>>>(x, conv_w, conv_b, pxt);

    // 2. LN1 -> xn (bf16)
    ln_kernel<<<(int)(M / 8), 256>>>(pxt, norm1_w, norm1_b, pxn);

    // 3. QKV GEMM -> bf16 qkv
    {
        EpiQKVb e{pqkv};
        bgemm_kernel<EpiQKVb><<<dim3(3, (unsigned)(M / BM)), 256>>>(pxn, pwq, 128, e);
    }

    // 4. attention (tensor-core) -> abuf (bf16)
    win_attn_kernel <<<BS * 256, 256>>>(pqkv, pabuf);
    grid_attn_kernel<<<BS * 256, 256>>>(pqkv, pabuf);

    // 5. proj GEMM + ls1 + residual -> xt2 (fp32)
    {
        EpiProj e{proj_b, ls1, pxt, pxt2};
        bgemm_kernel<EpiProj><<<dim3(1, (unsigned)(M / BM)), 256>>>(pabuf, pwp, 128, e);
    }

    // 6. LN2 -> xn (bf16)
    ln_kernel<<<(int)(M / 8), 256>>>(pxt2, norm2_w, norm2_b, pxn);

    // 7. FC1 + bias + GELU -> h (bf16)
    {
        EpiGelu e{fc1_b, ph};
        bgemm_kernel<EpiGelu><<<dim3(4, (unsigned)(M / BM)), 256>>>(pxn, pw1, 128, e);
    }

    // 8. FC2 + bias + ls2 + residual -> y (fp32)
    {
        EpiFc2 e{fc2_b, ls2, pxt2, py};
        bgemm_kernel<EpiFc2><<<dim3(1, (unsigned)(M / BM)), 256>>>(ph, pw2, 512, e);
    }

    // 9. transpose -> d_out
    transpose_out_kernel<<<dim3(P / 32, C / 32, BS), dim3(32, 8)>>>(py, out);

    (void)in_sizes; (void)n_in; (void)out_size;
}